// round 1
// baseline (speedup 1.0000x reference)
#include <cuda_runtime.h>
#include <math.h>

#define NN 512
#define CC 128
#define RR (NN*NN)   // 262144 rows (i*512+j)

// ---------------- scratch (device globals; no allocations) ----------------
__device__ float g_xn[(size_t)RR * CC];   // LN(x), row-major [ij][c]
__device__ float g_gate[(size_t)RR * CC]; // sigmoid(xn @ g_out_w^T), [ij][c]
__device__ float g_a[(size_t)CC * RR];    // a[d][i*512+k]
__device__ float g_b[(size_t)CC * RR];    // b[d][j*512+k]
__device__ float g_t[(size_t)CC * RR];    // t[d][i*512+j]
__device__ float g_mu[RR];
__device__ float g_rs[RR];

__device__ __forceinline__ float sigmoidf_(float x) {
    return 1.0f / (1.0f + __expf(-x));
}

// ---------------- K1: input LayerNorm (warp per row) ----------------
__global__ void k_ln_in(const float* __restrict__ x,
                        const float* __restrict__ w,
                        const float* __restrict__ b) {
    int row = blockIdx.x * 8 + (threadIdx.x >> 5);
    int lane = threadIdx.x & 31;
    const float4 v = reinterpret_cast<const float4*>(x + (size_t)row * CC)[lane];
    float s = v.x + v.y + v.z + v.w;
    float q = v.x*v.x + v.y*v.y + v.z*v.z + v.w*v.w;
    #pragma unroll
    for (int o = 16; o; o >>= 1) {
        s += __shfl_xor_sync(0xffffffffu, s, o);
        q += __shfl_xor_sync(0xffffffffu, q, o);
    }
    float mu = s * (1.0f / CC);
    float var = q * (1.0f / CC) - mu * mu;
    float rs = rsqrtf(var + 1e-5f);
    float4 wv = reinterpret_cast<const float4*>(w)[lane];
    float4 bv = reinterpret_cast<const float4*>(b)[lane];
    float4 o4;
    o4.x = (v.x - mu) * rs * wv.x + bv.x;
    o4.y = (v.y - mu) * rs * wv.y + bv.y;
    o4.z = (v.z - mu) * rs * wv.z + bv.z;
    o4.w = (v.w - mu) * rs * wv.w + bv.w;
    reinterpret_cast<float4*>(g_xn + (size_t)row * CC)[lane] = o4;
}

// ---------------- K2: fused dual GEMM (p_in, g_in) + gating + d-major scatter
// C tile: BM=128 rows x BN=64 cols, for BOTH weight sets. 256 threads,
// per-thread 8x4 accum x2. K=128 in BK=8 slices.
__global__ void __launch_bounds__(256) k_gemm_in(const float* __restrict__ pw,
                                                 const float* __restrict__ gw) {
    __shared__ float As[8][128];
    __shared__ float Ps[8][64];
    __shared__ float Gs[8][64];
    const int tid  = threadIdx.x;
    const int row0 = blockIdx.x * 128;
    const int n0   = blockIdx.y * 64;
    const int tr = tid >> 4, tc = tid & 15;
    const int ar = tid >> 1, ac = (tid & 1) * 4;
    const int wsel = tid >> 7;         // 0 -> p weights, 1 -> g weights
    const int wi = tid & 127;
    const int wr = wi >> 1, wc = (wi & 1) * 4;
    const float* wptr = wsel ? gw : pw;
    float* wsm = wsel ? &Gs[0][0] : &Ps[0][0];

    float accp[8][4]; float accg[8][4];
    #pragma unroll
    for (int i = 0; i < 8; ++i)
        #pragma unroll
        for (int j = 0; j < 4; ++j) { accp[i][j] = 0.f; accg[i][j] = 0.f; }

    for (int k0 = 0; k0 < 128; k0 += 8) {
        float4 av = *reinterpret_cast<const float4*>(g_xn + (size_t)(row0 + ar) * 128 + k0 + ac);
        As[ac + 0][ar] = av.x; As[ac + 1][ar] = av.y;
        As[ac + 2][ar] = av.z; As[ac + 3][ar] = av.w;
        float4 wv = *reinterpret_cast<const float4*>(wptr + (size_t)(n0 + wr) * 128 + k0 + wc);
        wsm[(wc + 0) * 64 + wr] = wv.x; wsm[(wc + 1) * 64 + wr] = wv.y;
        wsm[(wc + 2) * 64 + wr] = wv.z; wsm[(wc + 3) * 64 + wr] = wv.w;
        __syncthreads();
        #pragma unroll
        for (int k = 0; k < 8; ++k) {
            float af[8];
            *reinterpret_cast<float4*>(&af[0]) = *reinterpret_cast<const float4*>(&As[k][tr * 8]);
            *reinterpret_cast<float4*>(&af[4]) = *reinterpret_cast<const float4*>(&As[k][tr * 8 + 4]);
            float4 pf = *reinterpret_cast<const float4*>(&Ps[k][tc * 4]);
            float4 gf = *reinterpret_cast<const float4*>(&Gs[k][tc * 4]);
            #pragma unroll
            for (int i = 0; i < 8; ++i) {
                accp[i][0] += af[i] * pf.x; accp[i][1] += af[i] * pf.y;
                accp[i][2] += af[i] * pf.z; accp[i][3] += af[i] * pf.w;
                accg[i][0] += af[i] * gf.x; accg[i][1] += af[i] * gf.y;
                accg[i][2] += af[i] * gf.z; accg[i][3] += af[i] * gf.w;
            }
        }
        __syncthreads();
    }
    #pragma unroll
    for (int i = 0; i < 8; ++i) {
        int row = row0 + tr * 8 + i;
        #pragma unroll
        for (int j = 0; j < 4; ++j) {
            int col = n0 + tc * 4 + j;                 // 0..255
            float hv = accp[i][j] * sigmoidf_(accg[i][j]);
            float* dst = (col < 128) ? g_a : g_b;
            dst[(size_t)(col & 127) * RR + row] = hv;  // d-major scatter
        }
    }
}

// ---------------- K2b: gate GEMM sigmoid(xn @ g_out_w^T) ----------------
__global__ void __launch_bounds__(256) k_gemm_gate(const float* __restrict__ gow) {
    __shared__ float As[8][128];
    __shared__ float Ws[8][64];
    const int tid  = threadIdx.x;
    const int row0 = blockIdx.x * 128;
    const int n0   = blockIdx.y * 64;
    const int tr = tid >> 4, tc = tid & 15;
    const int ar = tid >> 1, ac = (tid & 1) * 4;
    const int wr = (tid & 127) >> 1, wc = (tid & 1) * 4;

    float acc[8][4];
    #pragma unroll
    for (int i = 0; i < 8; ++i)
        #pragma unroll
        for (int j = 0; j < 4; ++j) acc[i][j] = 0.f;

    for (int k0 = 0; k0 < 128; k0 += 8) {
        float4 av = *reinterpret_cast<const float4*>(g_xn + (size_t)(row0 + ar) * 128 + k0 + ac);
        As[ac + 0][ar] = av.x; As[ac + 1][ar] = av.y;
        As[ac + 2][ar] = av.z; As[ac + 3][ar] = av.w;
        if (tid < 128) {
            float4 wv = *reinterpret_cast<const float4*>(gow + (size_t)(n0 + wr) * 128 + k0 + wc);
            Ws[wc + 0][wr] = wv.x; Ws[wc + 1][wr] = wv.y;
            Ws[wc + 2][wr] = wv.z; Ws[wc + 3][wr] = wv.w;
        }
        __syncthreads();
        #pragma unroll
        for (int k = 0; k < 8; ++k) {
            float af[8];
            *reinterpret_cast<float4*>(&af[0]) = *reinterpret_cast<const float4*>(&As[k][tr * 8]);
            *reinterpret_cast<float4*>(&af[4]) = *reinterpret_cast<const float4*>(&As[k][tr * 8 + 4]);
            float4 wf = *reinterpret_cast<const float4*>(&Ws[k][tc * 4]);
            #pragma unroll
            for (int i = 0; i < 8; ++i) {
                acc[i][0] += af[i] * wf.x; acc[i][1] += af[i] * wf.y;
                acc[i][2] += af[i] * wf.z; acc[i][3] += af[i] * wf.w;
            }
        }
        __syncthreads();
    }
    #pragma unroll
    for (int i = 0; i < 8; ++i) {
        int row = row0 + tr * 8 + i;
        float4 o;
        o.x = sigmoidf_(acc[i][0]); o.y = sigmoidf_(acc[i][1]);
        o.z = sigmoidf_(acc[i][2]); o.w = sigmoidf_(acc[i][3]);
        *reinterpret_cast<float4*>(g_gate + (size_t)row * 128 + n0 + tc * 4) = o;
    }
}

// ---------------- K3: einsum, 128 batched 512x512x512 NT SGEMMs ----------------
__global__ void __launch_bounds__(256) k_einsum() {
    __shared__ float As[8][128];
    __shared__ float Bs[8][128];
    const int d = blockIdx.z;
    const float* A = g_a + (size_t)d * RR;
    const float* B = g_b + (size_t)d * RR;
    float* Cp = g_t + (size_t)d * RR;
    const int row0 = blockIdx.x * 128, col0 = blockIdx.y * 128;
    const int tid = threadIdx.x;
    const int tr = tid >> 4, tc = tid & 15;
    const int lr = tid >> 1, lc = (tid & 1) * 4;

    float acc[8][8];
    #pragma unroll
    for (int i = 0; i < 8; ++i)
        #pragma unroll
        for (int j = 0; j < 8; ++j) acc[i][j] = 0.f;

    for (int k0 = 0; k0 < 512; k0 += 8) {
        float4 av = *reinterpret_cast<const float4*>(A + (size_t)(row0 + lr) * 512 + k0 + lc);
        As[lc + 0][lr] = av.x; As[lc + 1][lr] = av.y;
        As[lc + 2][lr] = av.z; As[lc + 3][lr] = av.w;
        float4 bv = *reinterpret_cast<const float4*>(B + (size_t)(col0 + lr) * 512 + k0 + lc);
        Bs[lc + 0][lr] = bv.x; Bs[lc + 1][lr] = bv.y;
        Bs[lc + 2][lr] = bv.z; Bs[lc + 3][lr] = bv.w;
        __syncthreads();
        #pragma unroll
        for (int k = 0; k < 8; ++k) {
            float af[8], bf[8];
            *reinterpret_cast<float4*>(&af[0]) = *reinterpret_cast<const float4*>(&As[k][tr * 8]);
            *reinterpret_cast<float4*>(&af[4]) = *reinterpret_cast<const float4*>(&As[k][tr * 8 + 4]);
            *reinterpret_cast<float4*>(&bf[0]) = *reinterpret_cast<const float4*>(&Bs[k][tc * 8]);
            *reinterpret_cast<float4*>(&bf[4]) = *reinterpret_cast<const float4*>(&Bs[k][tc * 8 + 4]);
            #pragma unroll
            for (int i = 0; i < 8; ++i)
                #pragma unroll
                for (int j = 0; j < 8; ++j)
                    acc[i][j] += af[i] * bf[j];
        }
        __syncthreads();
    }
    #pragma unroll
    for (int i = 0; i < 8; ++i) {
        int row = row0 + tr * 8 + i;
        float4 c0 = make_float4(acc[i][0], acc[i][1], acc[i][2], acc[i][3]);
        float4 c1 = make_float4(acc[i][4], acc[i][5], acc[i][6], acc[i][7]);
        *reinterpret_cast<float4*>(Cp + (size_t)row * 512 + col0 + tc * 8)     = c0;
        *reinterpret_cast<float4*>(Cp + (size_t)row * 512 + col0 + tc * 8 + 4) = c1;
    }
}

// ---------------- K4: per-(i,j) LN stats over d ----------------
__global__ void k_stats() {
    int ij = blockIdx.x * 256 + threadIdx.x;
    float s = 0.f, q = 0.f;
    #pragma unroll 8
    for (int d = 0; d < 128; ++d) {
        float v = g_t[(size_t)d * RR + ij];
        s += v; q += v * v;
    }
    float mu = s * (1.0f / 128.0f);
    float var = q * (1.0f / 128.0f) - mu * mu;
    g_mu[ij] = mu;
    g_rs[ij] = rsqrtf(var + 1e-5f);
}

// ---------------- K5: output GEMM with fused LN(t) and gate ----------------
__global__ void __launch_bounds__(256) k_gemm_out(const float* __restrict__ now,
                                                  const float* __restrict__ nob,
                                                  const float* __restrict__ powt,
                                                  float* __restrict__ out) {
    __shared__ float As[8][128];
    __shared__ float Ws[8][128];
    __shared__ float smu[128], srs[128], swd[128], sbd[128];
    const int tid  = threadIdx.x;
    const int row0 = blockIdx.x * 128;
    if (tid < 128) {
        smu[tid] = g_mu[row0 + tid];
        srs[tid] = g_rs[row0 + tid];
        swd[tid] = now[tid];
        sbd[tid] = nob[tid];
    }
    __syncthreads();
    const int tr = tid >> 4, tc = tid & 15;
    const int am = (tid & 31) * 4;  // row within tile
    const int ak = tid >> 5;        // k within slice
    const int wr = tid >> 1, wc = (tid & 1) * 4;

    float acc[8][8];
    #pragma unroll
    for (int i = 0; i < 8; ++i)
        #pragma unroll
        for (int j = 0; j < 8; ++j) acc[i][j] = 0.f;

    for (int k0 = 0; k0 < 128; k0 += 8) {
        // A tile: t is d-major -> this load is already k-major; fuse LN here
        float4 tv = *reinterpret_cast<const float4*>(g_t + (size_t)(k0 + ak) * RR + row0 + am);
        float wk = swd[k0 + ak], bk = sbd[k0 + ak];
        float4 a4;
        a4.x = (tv.x - smu[am + 0]) * srs[am + 0] * wk + bk;
        a4.y = (tv.y - smu[am + 1]) * srs[am + 1] * wk + bk;
        a4.z = (tv.z - smu[am + 2]) * srs[am + 2] * wk + bk;
        a4.w = (tv.w - smu[am + 3]) * srs[am + 3] * wk + bk;
        *reinterpret_cast<float4*>(&As[ak][am]) = a4;
        float4 wv = *reinterpret_cast<const float4*>(powt + (size_t)wr * 128 + k0 + wc);
        Ws[wc + 0][wr] = wv.x; Ws[wc + 1][wr] = wv.y;
        Ws[wc + 2][wr] = wv.z; Ws[wc + 3][wr] = wv.w;
        __syncthreads();
        #pragma unroll
        for (int k = 0; k < 8; ++k) {
            float af[8], bf[8];
            *reinterpret_cast<float4*>(&af[0]) = *reinterpret_cast<const float4*>(&As[k][tr * 8]);
            *reinterpret_cast<float4*>(&af[4]) = *reinterpret_cast<const float4*>(&As[k][tr * 8 + 4]);
            *reinterpret_cast<float4*>(&bf[0]) = *reinterpret_cast<const float4*>(&Ws[k][tc * 8]);
            *reinterpret_cast<float4*>(&bf[4]) = *reinterpret_cast<const float4*>(&Ws[k][tc * 8 + 4]);
            #pragma unroll
            for (int i = 0; i < 8; ++i)
                #pragma unroll
                for (int j = 0; j < 8; ++j)
                    acc[i][j] += af[i] * bf[j];
        }
        __syncthreads();
    }
    #pragma unroll
    for (int i = 0; i < 8; ++i) {
        int row = row0 + tr * 8 + i;
        float4 gt0 = *reinterpret_cast<const float4*>(g_gate + (size_t)row * 128 + tc * 8);
        float4 gt1 = *reinterpret_cast<const float4*>(g_gate + (size_t)row * 128 + tc * 8 + 4);
        float4 o0 = make_float4(acc[i][0] * gt0.x, acc[i][1] * gt0.y,
                                acc[i][2] * gt0.z, acc[i][3] * gt0.w);
        float4 o1 = make_float4(acc[i][4] * gt1.x, acc[i][5] * gt1.y,
                                acc[i][6] * gt1.z, acc[i][7] * gt1.w);
        *reinterpret_cast<float4*>(out + (size_t)row * 128 + tc * 8)     = o0;
        *reinterpret_cast<float4*>(out + (size_t)row * 128 + tc * 8 + 4) = o1;
    }
}

// ---------------- launch ----------------
extern "C" void kernel_launch(void* const* d_in, const int* in_sizes, int n_in,
                              void* d_out, int out_size) {
    (void)in_sizes; (void)n_in; (void)out_size;
    const float* x    = (const float*)d_in[0];
    const float* niw  = (const float*)d_in[1];
    const float* nib  = (const float*)d_in[2];
    const float* piw  = (const float*)d_in[3];
    const float* giw  = (const float*)d_in[4];
    const float* noww = (const float*)d_in[5];
    const float* nob  = (const float*)d_in[6];
    const float* powt = (const float*)d_in[7];
    const float* gow  = (const float*)d_in[8];
    float* out = (float*)d_out;

    k_ln_in<<<RR / 8, 256>>>(x, niw, nib);
    k_gemm_in<<<dim3(RR / 128, 4), 256>>>(piw, giw);
    k_gemm_gate<<<dim3(RR / 128, 2), 256>>>(gow);
    k_einsum<<<dim3(4, 4, 128), 256>>>();
    k_stats<<<RR / 256, 256>>>();
    k_gemm_out<<<RR / 128, 256>>>(noww, nob, powt, out);
}

// round 3
// speedup vs baseline: 1.9447x; 1.9447x over previous
#include <cuda_runtime.h>
#include <math.h>
#include <stdint.h>

#define NN 512
#define CC 128
#define RR (NN*NN)   // 262144 rows (i*512+j)

// ---------------- scratch (device globals; no allocations) ----------------
__device__ float g_xn[(size_t)RR * CC];   // LN(x), row-major [ij][c]
__device__ float g_gate[(size_t)RR * CC]; // sigmoid(xn @ g_out_w^T), [ij][c]
__device__ float g_a[(size_t)CC * RR];    // a[d][i*512+k]
__device__ float g_b[(size_t)CC * RR];    // b[d][j*512+k]
__device__ float g_t[(size_t)CC * RR];    // t[d][i*512+j]
__device__ float g_mu[RR];
__device__ float g_rs[RR];

__device__ __forceinline__ float sigmoidf_(float x) {
    return 1.0f / (1.0f + __expf(-x));
}

__device__ __forceinline__ uint32_t f2tf(float f) {
    uint32_t u;
    asm("cvt.rna.tf32.f32 %0, %1;" : "=r"(u) : "f"(f));
    return u;
}

// mma.sync m16n8k8 tf32, fp32 accumulate.
// CORRECT tf32 fragment map (PTX ISA / CUTLASS SM80_16x8x8_F32TF32TF32F32_TN):
//   A: a0=(g, t) a1=(g+8, t) a2=(g, t+4) a3=(g+8, t+4)   [t = lane&3, g = lane>>2]
//   B: b0=(k=t, n=g) b1=(k=t+4, n=g)
//   C: c0=(g,2t) c1=(g,2t+1) c2=(g+8,2t) c3=(g+8,2t+1)
__device__ __forceinline__ void mma_tf32(float* c,
                                         uint32_t a0, uint32_t a1, uint32_t a2, uint32_t a3,
                                         uint32_t b0, uint32_t b1) {
    asm volatile(
        "mma.sync.aligned.m16n8k8.row.col.f32.tf32.tf32.f32 "
        "{%0,%1,%2,%3}, {%4,%5,%6,%7}, {%8,%9}, {%0,%1,%2,%3};"
        : "+f"(c[0]), "+f"(c[1]), "+f"(c[2]), "+f"(c[3])
        : "r"(a0), "r"(a1), "r"(a2), "r"(a3), "r"(b0), "r"(b1));
}

__device__ __forceinline__ void cpa16(uint32_t saddr, const void* gptr) {
    asm volatile("cp.async.cg.shared.global [%0], [%1], 16;" :: "r"(saddr), "l"(gptr));
}
__device__ __forceinline__ void cpa_commit() { asm volatile("cp.async.commit_group;"); }
template<int N> __device__ __forceinline__ void cpa_wait() {
    asm volatile("cp.async.wait_group %0;" :: "n"(N));
}

// ---------------- K1: input LayerNorm (warp per row) ----------------
__global__ void k_ln_in(const float* __restrict__ x,
                        const float* __restrict__ w,
                        const float* __restrict__ b) {
    int row = blockIdx.x * 8 + (threadIdx.x >> 5);
    int lane = threadIdx.x & 31;
    const float4 v = reinterpret_cast<const float4*>(x + (size_t)row * CC)[lane];
    float s = v.x + v.y + v.z + v.w;
    float q = v.x*v.x + v.y*v.y + v.z*v.z + v.w*v.w;
    #pragma unroll
    for (int o = 16; o; o >>= 1) {
        s += __shfl_xor_sync(0xffffffffu, s, o);
        q += __shfl_xor_sync(0xffffffffu, q, o);
    }
    float mu = s * (1.0f / CC);
    float var = q * (1.0f / CC) - mu * mu;
    float rs = rsqrtf(var + 1e-5f);
    float4 wv = reinterpret_cast<const float4*>(w)[lane];
    float4 bv = reinterpret_cast<const float4*>(b)[lane];
    float4 o4;
    o4.x = (v.x - mu) * rs * wv.x + bv.x;
    o4.y = (v.y - mu) * rs * wv.y + bv.y;
    o4.z = (v.z - mu) * rs * wv.z + bv.z;
    o4.w = (v.w - mu) * rs * wv.w + bv.w;
    reinterpret_cast<float4*>(g_xn + (size_t)row * CC)[lane] = o4;
}

// ---------------- K2: fused dual GEMM (p_in, g_in) + gating + d-major write
__global__ void __launch_bounds__(256) k_gemm_in(const float* __restrict__ pw,
                                                 const float* __restrict__ gw) {
    __shared__ __align__(16) uint32_t sm[6400]; // As 64x20 | Wp 128x20 | Wg 128x20
    uint32_t* As = sm;
    uint32_t* Wp = sm + 1280;
    uint32_t* Wg = sm + 3840;

    const int tid = threadIdx.x;
    const int row0 = blockIdx.x * 64;
    const int n0   = blockIdx.y * 128;
    const int w  = tid >> 5;
    const int wm = w & 3;
    const int hf = w >> 2;
    const int lane = tid & 31;
    const int g  = lane >> 2;
    const int t  = lane & 3;
    const int t2 = t * 2;

    float ap[8][4], ag[8][4];
    #pragma unroll
    for (int i = 0; i < 8; ++i)
        #pragma unroll
        for (int j = 0; j < 4; ++j) { ap[i][j] = 0.f; ag[i][j] = 0.f; }

    for (int k0 = 0; k0 < 128; k0 += 16) {
        // stage A (64x16)
        {
            int row = tid >> 2, kg = tid & 3;
            float4 v = *reinterpret_cast<const float4*>(
                g_xn + (size_t)(row0 + row) * 128 + k0 + kg * 4);
            uint32_t* d = &As[row * 20 + kg * 4];
            d[0] = f2tf(v.x); d[1] = f2tf(v.y); d[2] = f2tf(v.z); d[3] = f2tf(v.w);
        }
        // stage weights (128x16 each)
        #pragma unroll
        for (int s = 0; s < 2; ++s) {
            int slot = tid * 2 + s;
            int col = slot >> 2, kg = slot & 3;
            float4 vp = *reinterpret_cast<const float4*>(
                pw + (size_t)(n0 + col) * 128 + k0 + kg * 4);
            uint32_t* dp = &Wp[col * 20 + kg * 4];
            dp[0] = f2tf(vp.x); dp[1] = f2tf(vp.y); dp[2] = f2tf(vp.z); dp[3] = f2tf(vp.w);
            float4 vg = *reinterpret_cast<const float4*>(
                gw + (size_t)(n0 + col) * 128 + k0 + kg * 4);
            uint32_t* dg = &Wg[col * 20 + kg * 4];
            dg[0] = f2tf(vg.x); dg[1] = f2tf(vg.y); dg[2] = f2tf(vg.z); dg[3] = f2tf(vg.w);
        }
        __syncthreads();
        #pragma unroll
        for (int kk = 0; kk < 16; kk += 8) {
            int arow = wm * 16 + g;
            uint32_t a0 = As[arow * 20 + kk + t];
            uint32_t a1 = As[(arow + 8) * 20 + kk + t];
            uint32_t a2 = As[arow * 20 + kk + t + 4];
            uint32_t a3 = As[(arow + 8) * 20 + kk + t + 4];
            #pragma unroll
            for (int nt = 0; nt < 8; ++nt) {
                int ncol = hf * 64 + nt * 8 + g;
                uint32_t pb0 = Wp[ncol * 20 + kk + t];
                uint32_t pb1 = Wp[ncol * 20 + kk + t + 4];
                mma_tf32(ap[nt], a0, a1, a2, a3, pb0, pb1);
                uint32_t gb0 = Wg[ncol * 20 + kk + t];
                uint32_t gb1 = Wg[ncol * 20 + kk + t + 4];
                mma_tf32(ag[nt], a0, a1, a2, a3, gb0, gb1);
            }
        }
        __syncthreads();
    }

    // gated values
    float hv[8][4];
    #pragma unroll
    for (int nt = 0; nt < 8; ++nt)
        #pragma unroll
        for (int c = 0; c < 4; ++c)
            hv[nt][c] = ap[nt][c] * sigmoidf_(ag[nt][c]);

    // chunked smem transpose -> coalesced d-major stores
    float* plane = (blockIdx.y == 0) ? g_a : g_b;
    float* sc = reinterpret_cast<float*>(sm); // 32 cols x stride 68
    for (int ch = 0; ch < 4; ++ch) {
        __syncthreads();
        if (hf == (ch >> 1)) {
            int r = wm * 16 + g;
            #pragma unroll
            for (int q = 0; q < 4; ++q) {
                int nt = (ch & 1) * 4 + q;
                int c0 = q * 8 + t2;
                sc[(c0 + 0) * 68 + r]     = hv[nt][0];
                sc[(c0 + 1) * 68 + r]     = hv[nt][1];
                sc[(c0 + 0) * 68 + r + 8] = hv[nt][2];
                sc[(c0 + 1) * 68 + r + 8] = hv[nt][3];
            }
        }
        __syncthreads();
        #pragma unroll
        for (int s = 0; s < 2; ++s) {
            int slot = tid * 2 + s;
            int colc = slot >> 4, f4 = slot & 15;
            float4 v = *reinterpret_cast<const float4*>(&sc[colc * 68 + f4 * 4]);
            *reinterpret_cast<float4*>(
                &plane[(size_t)(ch * 32 + colc) * RR + row0 + f4 * 4]) = v;
        }
    }
}

// ---------------- K2b: gate GEMM sigmoid(xn @ g_out_w^T), tf32 mma ----------------
__global__ void __launch_bounds__(256) k_gemm_gate(const float* __restrict__ gow) {
    __shared__ __align__(16) uint32_t sm[3840]; // As 64x20 | Ws 128x20
    uint32_t* As = sm;
    uint32_t* Ws = sm + 1280;

    const int tid = threadIdx.x;
    const int row0 = blockIdx.x * 64;
    const int w  = tid >> 5;
    const int wm = w & 3;
    const int hf = w >> 2;
    const int lane = tid & 31;
    const int g  = lane >> 2;
    const int t  = lane & 3;
    const int t2 = t * 2;

    float acc[8][4];
    #pragma unroll
    for (int i = 0; i < 8; ++i)
        #pragma unroll
        for (int j = 0; j < 4; ++j) acc[i][j] = 0.f;

    for (int k0 = 0; k0 < 128; k0 += 16) {
        {
            int row = tid >> 2, kg = tid & 3;
            float4 v = *reinterpret_cast<const float4*>(
                g_xn + (size_t)(row0 + row) * 128 + k0 + kg * 4);
            uint32_t* d = &As[row * 20 + kg * 4];
            d[0] = f2tf(v.x); d[1] = f2tf(v.y); d[2] = f2tf(v.z); d[3] = f2tf(v.w);
        }
        #pragma unroll
        for (int s = 0; s < 2; ++s) {
            int slot = tid * 2 + s;
            int col = slot >> 2, kg = slot & 3;
            float4 vw = *reinterpret_cast<const float4*>(
                gow + (size_t)col * 128 + k0 + kg * 4);
            uint32_t* d = &Ws[col * 20 + kg * 4];
            d[0] = f2tf(vw.x); d[1] = f2tf(vw.y); d[2] = f2tf(vw.z); d[3] = f2tf(vw.w);
        }
        __syncthreads();
        #pragma unroll
        for (int kk = 0; kk < 16; kk += 8) {
            int arow = wm * 16 + g;
            uint32_t a0 = As[arow * 20 + kk + t];
            uint32_t a1 = As[(arow + 8) * 20 + kk + t];
            uint32_t a2 = As[arow * 20 + kk + t + 4];
            uint32_t a3 = As[(arow + 8) * 20 + kk + t + 4];
            #pragma unroll
            for (int nt = 0; nt < 8; ++nt) {
                int ncol = hf * 64 + nt * 8 + g;
                uint32_t b0 = Ws[ncol * 20 + kk + t];
                uint32_t b1 = Ws[ncol * 20 + kk + t + 4];
                mma_tf32(acc[nt], a0, a1, a2, a3, b0, b1);
            }
        }
        __syncthreads();
    }
    #pragma unroll
    for (int nt = 0; nt < 8; ++nt) {
        int col = hf * 64 + nt * 8 + t2;
        int row = row0 + wm * 16 + g;
        float2 v0 = make_float2(sigmoidf_(acc[nt][0]), sigmoidf_(acc[nt][1]));
        float2 v1 = make_float2(sigmoidf_(acc[nt][2]), sigmoidf_(acc[nt][3]));
        *reinterpret_cast<float2*>(&g_gate[(size_t)row * 128 + col])       = v0;
        *reinterpret_cast<float2*>(&g_gate[(size_t)(row + 8) * 128 + col]) = v1;
    }
}

// ---------------- K3: einsum, 128 batched 512x512x512 NT GEMMs (tf32 mma) ---------
__global__ void __launch_bounds__(256, 2) k_einsum() {
    __shared__ __align__(16) uint32_t sm[10240]; // A[2]:128x20 | B[2]:128x20 (raw f32 bits)
    const int d = blockIdx.z;
    const float* A = g_a + (size_t)d * RR;
    const float* B = g_b + (size_t)d * RR;
    float* Cp = g_t + (size_t)d * RR;
    const int row0 = blockIdx.x * 128, col0 = blockIdx.y * 128;
    const int tid = threadIdx.x;
    const int w  = tid >> 5;
    const int wm = w >> 2;      // 0..1
    const int wn = w & 3;       // 0..3
    const int lane = tid & 31;
    const int g  = lane >> 2;
    const int t  = lane & 3;
    const int t2 = t * 2;

    const uint32_t sbase = (uint32_t)__cvta_generic_to_shared(sm);
    const int sA[2] = {0, 2560};
    const int sB[2] = {5120, 7680};

    float acc[4][4][4];
    #pragma unroll
    for (int i = 0; i < 4; ++i)
        #pragma unroll
        for (int j = 0; j < 4; ++j)
            #pragma unroll
            for (int c = 0; c < 4; ++c) acc[i][j][c] = 0.f;

    auto stage = [&](int buf, int ks) {
        int k0 = ks * 16;
        #pragma unroll
        for (int s = 0; s < 2; ++s) {
            int slot = tid * 2 + s;
            int row = slot >> 2, kg = slot & 3;
            cpa16(sbase + (sA[buf] + row * 20 + kg * 4) * 4,
                  A + (size_t)(row0 + row) * 512 + k0 + kg * 4);
            cpa16(sbase + (sB[buf] + row * 20 + kg * 4) * 4,
                  B + (size_t)(col0 + row) * 512 + k0 + kg * 4);
        }
    };

    stage(0, 0);
    cpa_commit();

    for (int ks = 0; ks < 32; ++ks) {
        if (ks < 31) { stage((ks + 1) & 1, ks + 1); cpa_commit(); }
        if (ks < 31) cpa_wait<1>(); else cpa_wait<0>();
        __syncthreads();

        const uint32_t* As = sm + sA[ks & 1];
        const uint32_t* Bs = sm + sB[ks & 1];
        #pragma unroll
        for (int kk = 0; kk < 16; kk += 8) {
            uint32_t af[4][4];
            #pragma unroll
            for (int mt = 0; mt < 4; ++mt) {
                int row = wm * 64 + mt * 16 + g;
                af[mt][0] = f2tf(__uint_as_float(As[row * 20 + kk + t]));
                af[mt][1] = f2tf(__uint_as_float(As[(row + 8) * 20 + kk + t]));
                af[mt][2] = f2tf(__uint_as_float(As[row * 20 + kk + t + 4]));
                af[mt][3] = f2tf(__uint_as_float(As[(row + 8) * 20 + kk + t + 4]));
            }
            #pragma unroll
            for (int nt = 0; nt < 4; ++nt) {
                int coln = wn * 32 + nt * 8 + g;
                uint32_t b0 = f2tf(__uint_as_float(Bs[coln * 20 + kk + t]));
                uint32_t b1 = f2tf(__uint_as_float(Bs[coln * 20 + kk + t + 4]));
                #pragma unroll
                for (int mt = 0; mt < 4; ++mt)
                    mma_tf32(acc[mt][nt], af[mt][0], af[mt][1], af[mt][2], af[mt][3], b0, b1);
            }
        }
        __syncthreads();
    }

    #pragma unroll
    for (int mt = 0; mt < 4; ++mt) {
        int r = row0 + wm * 64 + mt * 16 + g;
        #pragma unroll
        for (int nt = 0; nt < 4; ++nt) {
            int c = col0 + wn * 32 + nt * 8 + t2;
            *reinterpret_cast<float2*>(&Cp[(size_t)r * 512 + c]) =
                make_float2(acc[mt][nt][0], acc[mt][nt][1]);
            *reinterpret_cast<float2*>(&Cp[(size_t)(r + 8) * 512 + c]) =
                make_float2(acc[mt][nt][2], acc[mt][nt][3]);
        }
    }
}

// ---------------- K4: per-(i,j) LN stats over d ----------------
__global__ void k_stats() {
    int ij = blockIdx.x * 256 + threadIdx.x;
    float s = 0.f, q = 0.f;
    #pragma unroll 8
    for (int d = 0; d < 128; ++d) {
        float v = g_t[(size_t)d * RR + ij];
        s += v; q += v * v;
    }
    float mu = s * (1.0f / 128.0f);
    float var = q * (1.0f / 128.0f) - mu * mu;
    g_mu[ij] = mu;
    g_rs[ij] = rsqrtf(var + 1e-5f);
}

// ---------------- K5: output GEMM, LN fused into A staging, gate in epilogue ------
__global__ void __launch_bounds__(256) k_gemm_out(const float* __restrict__ now,
                                                  const float* __restrict__ nob,
                                                  const float* __restrict__ powt,
                                                  float* __restrict__ out) {
    __shared__ __align__(16) uint32_t sm[3840]; // As 64x20 | Ws 128x20
    __shared__ float smu[64], srs[64], swd[128], sbd[128];
    uint32_t* As = sm;
    uint32_t* Ws = sm + 1280;

    const int tid = threadIdx.x;
    const int row0 = blockIdx.x * 64;
    const int w  = tid >> 5;
    const int wm = w & 3;
    const int hf = w >> 2;
    const int lane = tid & 31;
    const int g  = lane >> 2;
    const int t  = lane & 3;
    const int t2 = t * 2;

    if (tid < 64) { smu[tid] = g_mu[row0 + tid]; srs[tid] = g_rs[row0 + tid]; }
    if (tid < 128) { swd[tid] = now[tid]; sbd[tid] = nob[tid]; }
    __syncthreads();

    float acc[8][4];
    #pragma unroll
    for (int i = 0; i < 8; ++i)
        #pragma unroll
        for (int j = 0; j < 4; ++j) acc[i][j] = 0.f;

    for (int k0 = 0; k0 < 128; k0 += 16) {
        {
            int dl = tid >> 4;              // 0..15
            int r4 = (tid & 15) * 4;        // 0..60
            float4 tv = *reinterpret_cast<const float4*>(
                g_t + (size_t)(k0 + dl) * RR + row0 + r4);
            float wk = swd[k0 + dl], bk = sbd[k0 + dl];
            As[(r4 + 0) * 20 + dl] = f2tf((tv.x - smu[r4 + 0]) * srs[r4 + 0] * wk + bk);
            As[(r4 + 1) * 20 + dl] = f2tf((tv.y - smu[r4 + 1]) * srs[r4 + 1] * wk + bk);
            As[(r4 + 2) * 20 + dl] = f2tf((tv.z - smu[r4 + 2]) * srs[r4 + 2] * wk + bk);
            As[(r4 + 3) * 20 + dl] = f2tf((tv.w - smu[r4 + 3]) * srs[r4 + 3] * wk + bk);
        }
        #pragma unroll
        for (int s = 0; s < 2; ++s) {
            int slot = tid * 2 + s;
            int col = slot >> 2, kg = slot & 3;
            float4 vw = *reinterpret_cast<const float4*>(
                powt + (size_t)col * 128 + k0 + kg * 4);
            uint32_t* dst = &Ws[col * 20 + kg * 4];
            dst[0] = f2tf(vw.x); dst[1] = f2tf(vw.y); dst[2] = f2tf(vw.z); dst[3] = f2tf(vw.w);
        }
        __syncthreads();
        #pragma unroll
        for (int kk = 0; kk < 16; kk += 8) {
            int arow = wm * 16 + g;
            uint32_t a0 = As[arow * 20 + kk + t];
            uint32_t a1 = As[(arow + 8) * 20 + kk + t];
            uint32_t a2 = As[arow * 20 + kk + t + 4];
            uint32_t a3 = As[(arow + 8) * 20 + kk + t + 4];
            #pragma unroll
            for (int nt = 0; nt < 8; ++nt) {
                int ncol = hf * 64 + nt * 8 + g;
                uint32_t b0 = Ws[ncol * 20 + kk + t];
                uint32_t b1 = Ws[ncol * 20 + kk + t + 4];
                mma_tf32(acc[nt], a0, a1, a2, a3, b0, b1);
            }
        }
        __syncthreads();
    }
    #pragma unroll
    for (int nt = 0; nt < 8; ++nt) {
        int col = hf * 64 + nt * 8 + t2;
        int row = row0 + wm * 16 + g;
        float2 gt0 = *reinterpret_cast<const float2*>(&g_gate[(size_t)row * 128 + col]);
        float2 gt1 = *reinterpret_cast<const float2*>(&g_gate[(size_t)(row + 8) * 128 + col]);
        *reinterpret_cast<float2*>(&out[(size_t)row * 128 + col]) =
            make_float2(acc[nt][0] * gt0.x, acc[nt][1] * gt0.y);
        *reinterpret_cast<float2*>(&out[(size_t)(row + 8) * 128 + col]) =
            make_float2(acc[nt][2] * gt1.x, acc[nt][3] * gt1.y);
    }
}

// ---------------- launch ----------------
extern "C" void kernel_launch(void* const* d_in, const int* in_sizes, int n_in,
                              void* d_out, int out_size) {
    (void)in_sizes; (void)n_in; (void)out_size;
    const float* x    = (const float*)d_in[0];
    const float* niw  = (const float*)d_in[1];
    const float* nib  = (const float*)d_in[2];
    const float* piw  = (const float*)d_in[3];
    const float* giw  = (const float*)d_in[4];
    const float* noww = (const float*)d_in[5];
    const float* nob  = (const float*)d_in[6];
    const float* powt = (const float*)d_in[7];
    const float* gow  = (const float*)d_in[8];
    float* out = (float*)d_out;

    k_ln_in<<<RR / 8, 256>>>(x, niw, nib);
    k_gemm_in<<<dim3(RR / 64, 2), 256>>>(piw, giw);
    k_gemm_gate<<<RR / 64, 256>>>(gow);
    k_einsum<<<dim3(4, 4, 128), 256>>>();
    k_stats<<<RR / 256, 256>>>();
    k_gemm_out<<<RR / 64, 256>>>(noww, nob, powt, out);
}

// round 4
// speedup vs baseline: 2.0006x; 1.0287x over previous
#include <cuda_runtime.h>
#include <math.h>
#include <stdint.h>

#define NN 512
#define CC 128
#define RR (NN*NN)   // 262144 rows (i*512+j)

// ---------------- scratch (device globals; no allocations) ----------------
__device__ float g_gate[(size_t)RR * CC]; // sigmoid(xn @ g_out_w^T), [ij][c]
__device__ float g_a[(size_t)CC * RR];    // a[d][i*512+k]  (tf32 bit patterns)
__device__ float g_b[(size_t)CC * RR];    // b[d][j*512+k]  (tf32 bit patterns)
__device__ float g_t[(size_t)CC * RR];    // t[d][i*512+j]  (fp32)

__device__ __forceinline__ float sigmoidf_(float x) {
    return 1.0f / (1.0f + __expf(-x));
}

__device__ __forceinline__ uint32_t f2tf(float f) {
    uint32_t u;
    asm("cvt.rna.tf32.f32 %0, %1;" : "=r"(u) : "f"(f));
    return u;
}

// tf32 m16n8k8 fragment map (PTX ISA):
//   A: a0=(g,t) a1=(g+8,t) a2=(g,t+4) a3=(g+8,t+4)   [t=lane&3, g=lane>>2]
//   B: b0=(k=t,n=g) b1=(k=t+4,n=g)
//   C: c0=(g,2t) c1=(g,2t+1) c2=(g+8,2t) c3=(g+8,2t+1)
__device__ __forceinline__ void mma_tf32(float* c,
                                         uint32_t a0, uint32_t a1, uint32_t a2, uint32_t a3,
                                         uint32_t b0, uint32_t b1) {
    asm volatile(
        "mma.sync.aligned.m16n8k8.row.col.f32.tf32.tf32.f32 "
        "{%0,%1,%2,%3}, {%4,%5,%6,%7}, {%8,%9}, {%0,%1,%2,%3};"
        : "+f"(c[0]), "+f"(c[1]), "+f"(c[2]), "+f"(c[3])
        : "r"(a0), "r"(a1), "r"(a2), "r"(a3), "r"(b0), "r"(b1));
}

__device__ __forceinline__ void cpa16(uint32_t saddr, const void* gptr) {
    asm volatile("cp.async.cg.shared.global [%0], [%1], 16;" :: "r"(saddr), "l"(gptr));
}
__device__ __forceinline__ void cpa_commit() { asm volatile("cp.async.commit_group;"); }
template<int N> __device__ __forceinline__ void cpa_wait() {
    asm volatile("cp.async.wait_group %0;" :: "n"(N));
}

// =================== K1: fused LN + dual gemm (p,g) + gate gemm ===================
// Block: 128 rows. A tile (LN'd, tf32) resident in smem. 640 output cols in
// 64-col chunks: 4 paired p/g chunks -> gated, transposed, d-major stores to
// g_a/g_b (as tf32 bits); 2 gate chunks -> row-major g_gate.
// smem: A 128x132 | Wp 64x132 | Wg 64x132 | sw 128 | sb 128  = 136192 B
#define F_A  0
#define F_WP 67584
#define F_WG 101376
#define F_SW 135168
#define F_SB 135680
#define F_TOTAL 136192

__global__ void __launch_bounds__(256) k_front(const float* __restrict__ x,
                                               const float* __restrict__ niw,
                                               const float* __restrict__ nib,
                                               const float* __restrict__ pw,
                                               const float* __restrict__ gw,
                                               const float* __restrict__ gow) {
    extern __shared__ __align__(16) char smraw[];
    float*    Af  = reinterpret_cast<float*>(smraw + F_A);
    uint32_t* Au  = reinterpret_cast<uint32_t*>(smraw + F_A);
    float*    Wpf = reinterpret_cast<float*>(smraw + F_WP);
    uint32_t* Wpu = reinterpret_cast<uint32_t*>(smraw + F_WP);
    float*    Wgf = reinterpret_cast<float*>(smraw + F_WG);
    uint32_t* Wgu = reinterpret_cast<uint32_t*>(smraw + F_WG);
    float*    sw  = reinterpret_cast<float*>(smraw + F_SW);
    float*    sb  = reinterpret_cast<float*>(smraw + F_SB);

    const int tid = threadIdx.x;
    const int row0 = blockIdx.x * 128;
    const uint32_t sbase = (uint32_t)__cvta_generic_to_shared(smraw);
    const int w = tid >> 5;
    const int lane = tid & 31;
    const int g = lane >> 2;
    const int t = lane & 3;
    const int t2 = t * 2;

    // ---- load x tile ----
    for (int s = tid; s < 4096; s += 256) {
        int row = s >> 5, kg = s & 31;
        cpa16(sbase + (uint32_t)(F_A) + (row * 132 + kg * 4) * 4,
              x + (size_t)(row0 + row) * 128 + kg * 4);
    }
    if (tid < 128) { sw[tid] = niw[tid]; sb[tid] = nib[tid]; }
    cpa_commit(); cpa_wait<0>(); __syncthreads();

    // ---- LayerNorm in place (2 threads / row), convert to tf32 bits ----
    {
        int r = tid >> 1, half = tid & 1;
        int base = r * 132 + half * 64;
        float s = 0.f, q = 0.f;
        #pragma unroll 8
        for (int j = 0; j < 64; ++j) { float v = Af[base + j]; s += v; q += v * v; }
        s += __shfl_xor_sync(0xffffffffu, s, 1);
        q += __shfl_xor_sync(0xffffffffu, q, 1);
        float mu = s * (1.0f / 128.0f);
        float rs = rsqrtf(q * (1.0f / 128.0f) - mu * mu + 1e-5f);
        #pragma unroll 8
        for (int j = 0; j < 64; ++j) {
            int k = half * 64 + j;
            float v = Af[r * 132 + k];
            Au[r * 132 + k] = f2tf((v - mu) * rs * sw[k] + sb[k]);
        }
    }
    __syncthreads();

    // ---- 4 paired p/g chunks of 64 cols ----
    for (int c = 0; c < 4; ++c) {
        int n0 = c * 64;
        for (int s = tid; s < 2048; s += 256) {
            int col = s >> 5, kg = s & 31;
            cpa16(sbase + (uint32_t)(F_WP) + (col * 132 + kg * 4) * 4,
                  pw + (size_t)(n0 + col) * 128 + kg * 4);
            cpa16(sbase + (uint32_t)(F_WG) + (col * 132 + kg * 4) * 4,
                  gw + (size_t)(n0 + col) * 128 + kg * 4);
        }
        cpa_commit(); cpa_wait<0>(); __syncthreads();
        for (int s = tid; s < 8192; s += 256) {
            int col = s >> 7, k = s & 127;
            int idx = col * 132 + k;
            Wpu[idx] = f2tf(Wpf[idx]);
            Wgu[idx] = f2tf(Wgf[idx]);
        }
        __syncthreads();

        float accp[8][4], accg[8][4];
        #pragma unroll
        for (int i = 0; i < 8; ++i)
            #pragma unroll
            for (int j = 0; j < 4; ++j) { accp[i][j] = 0.f; accg[i][j] = 0.f; }

        const int arow = w * 16 + g;
        #pragma unroll 4
        for (int kk = 0; kk < 128; kk += 8) {
            uint32_t a0 = Au[arow * 132 + kk + t];
            uint32_t a1 = Au[(arow + 8) * 132 + kk + t];
            uint32_t a2 = Au[arow * 132 + kk + t + 4];
            uint32_t a3 = Au[(arow + 8) * 132 + kk + t + 4];
            #pragma unroll
            for (int nt = 0; nt < 8; ++nt) {
                int ncol = nt * 8 + g;
                uint32_t pb0 = Wpu[ncol * 132 + kk + t];
                uint32_t pb1 = Wpu[ncol * 132 + kk + t + 4];
                mma_tf32(accp[nt], a0, a1, a2, a3, pb0, pb1);
                uint32_t gb0 = Wgu[ncol * 132 + kk + t];
                uint32_t gb1 = Wgu[ncol * 132 + kk + t + 4];
                mma_tf32(accg[nt], a0, a1, a2, a3, gb0, gb1);
            }
        }
        __syncthreads();  // reuse Wp as transpose scratch

        uint32_t* sc = Wpu;  // [col 0..63][row 0..127] stride 132, tf32 bits
        #pragma unroll
        for (int nt = 0; nt < 8; ++nt) {
            int c0 = nt * 8 + t2;
            sc[(c0 + 0) * 132 + arow]     = f2tf(accp[nt][0] * sigmoidf_(accg[nt][0]));
            sc[(c0 + 1) * 132 + arow]     = f2tf(accp[nt][1] * sigmoidf_(accg[nt][1]));
            sc[(c0 + 0) * 132 + arow + 8] = f2tf(accp[nt][2] * sigmoidf_(accg[nt][2]));
            sc[(c0 + 1) * 132 + arow + 8] = f2tf(accp[nt][3] * sigmoidf_(accg[nt][3]));
        }
        __syncthreads();

        float* plane = (c < 2) ? g_a : g_b;
        int dc0 = (c & 1) * 64;
        for (int s = tid; s < 2048; s += 256) {
            int col = s >> 5, f4 = s & 31;
            float4 v = *reinterpret_cast<const float4*>(&Wpf[col * 132 + f4 * 4]);
            *reinterpret_cast<float4*>(
                &plane[(size_t)(dc0 + col) * RR + row0 + f4 * 4]) = v;
        }
        __syncthreads();
    }

    // ---- 2 gate chunks of 64 cols ----
    for (int c = 0; c < 2; ++c) {
        int n0 = c * 64;
        for (int s = tid; s < 2048; s += 256) {
            int col = s >> 5, kg = s & 31;
            cpa16(sbase + (uint32_t)(F_WP) + (col * 132 + kg * 4) * 4,
                  gow + (size_t)(n0 + col) * 128 + kg * 4);
        }
        cpa_commit(); cpa_wait<0>(); __syncthreads();
        for (int s = tid; s < 8192; s += 256) {
            int col = s >> 7, k = s & 127;
            int idx = col * 132 + k;
            Wpu[idx] = f2tf(Wpf[idx]);
        }
        __syncthreads();

        float acc[8][4];
        #pragma unroll
        for (int i = 0; i < 8; ++i)
            #pragma unroll
            for (int j = 0; j < 4; ++j) acc[i][j] = 0.f;

        const int arow = w * 16 + g;
        #pragma unroll 4
        for (int kk = 0; kk < 128; kk += 8) {
            uint32_t a0 = Au[arow * 132 + kk + t];
            uint32_t a1 = Au[(arow + 8) * 132 + kk + t];
            uint32_t a2 = Au[arow * 132 + kk + t + 4];
            uint32_t a3 = Au[(arow + 8) * 132 + kk + t + 4];
            #pragma unroll
            for (int nt = 0; nt < 8; ++nt) {
                int ncol = nt * 8 + g;
                uint32_t b0 = Wpu[ncol * 132 + kk + t];
                uint32_t b1 = Wpu[ncol * 132 + kk + t + 4];
                mma_tf32(acc[nt], a0, a1, a2, a3, b0, b1);
            }
        }
        #pragma unroll
        for (int nt = 0; nt < 8; ++nt) {
            int col = n0 + nt * 8 + t2;
            int row = row0 + w * 16 + g;
            *reinterpret_cast<float2*>(&g_gate[(size_t)row * 128 + col]) =
                make_float2(sigmoidf_(acc[nt][0]), sigmoidf_(acc[nt][1]));
            *reinterpret_cast<float2*>(&g_gate[(size_t)(row + 8) * 128 + col]) =
                make_float2(sigmoidf_(acc[nt][2]), sigmoidf_(acc[nt][3]));
        }
        __syncthreads();
    }
}

// =================== K2: einsum, 128 batched 512x512x512 NT GEMMs ===================
// Inputs are pre-rounded tf32 bit patterns -> zero cvts in the mainloop.
__global__ void __launch_bounds__(256, 2) k_einsum() {
    __shared__ __align__(16) uint32_t sm[10240]; // A[2]:128x20 | B[2]:128x20
    const int d = blockIdx.z;
    const float* A = g_a + (size_t)d * RR;
    const float* B = g_b + (size_t)d * RR;
    float* Cp = g_t + (size_t)d * RR;
    const int row0 = blockIdx.x * 128, col0 = blockIdx.y * 128;
    const int tid = threadIdx.x;
    const int w  = tid >> 5;
    const int wm = w >> 2;      // 0..1
    const int wn = w & 3;       // 0..3
    const int lane = tid & 31;
    const int g  = lane >> 2;
    const int t  = lane & 3;
    const int t2 = t * 2;

    const uint32_t sbase = (uint32_t)__cvta_generic_to_shared(sm);
    const int sA[2] = {0, 2560};
    const int sB[2] = {5120, 7680};

    float acc[4][4][4];
    #pragma unroll
    for (int i = 0; i < 4; ++i)
        #pragma unroll
        for (int j = 0; j < 4; ++j)
            #pragma unroll
            for (int c = 0; c < 4; ++c) acc[i][j][c] = 0.f;

    auto stage = [&](int buf, int ks) {
        int k0 = ks * 16;
        #pragma unroll
        for (int s = 0; s < 2; ++s) {
            int slot = tid * 2 + s;
            int row = slot >> 2, kg = slot & 3;
            cpa16(sbase + (sA[buf] + row * 20 + kg * 4) * 4,
                  A + (size_t)(row0 + row) * 512 + k0 + kg * 4);
            cpa16(sbase + (sB[buf] + row * 20 + kg * 4) * 4,
                  B + (size_t)(col0 + row) * 512 + k0 + kg * 4);
        }
    };

    stage(0, 0);
    cpa_commit();

    for (int ks = 0; ks < 32; ++ks) {
        if (ks < 31) { stage((ks + 1) & 1, ks + 1); cpa_commit(); }
        if (ks < 31) cpa_wait<1>(); else cpa_wait<0>();
        __syncthreads();

        const uint32_t* As = sm + sA[ks & 1];
        const uint32_t* Bs = sm + sB[ks & 1];
        #pragma unroll
        for (int kk = 0; kk < 16; kk += 8) {
            uint32_t af[4][4];
            #pragma unroll
            for (int mt = 0; mt < 4; ++mt) {
                int row = wm * 64 + mt * 16 + g;
                af[mt][0] = As[row * 20 + kk + t];
                af[mt][1] = As[(row + 8) * 20 + kk + t];
                af[mt][2] = As[row * 20 + kk + t + 4];
                af[mt][3] = As[(row + 8) * 20 + kk + t + 4];
            }
            #pragma unroll
            for (int nt = 0; nt < 4; ++nt) {
                int coln = wn * 32 + nt * 8 + g;
                uint32_t b0 = Bs[coln * 20 + kk + t];
                uint32_t b1 = Bs[coln * 20 + kk + t + 4];
                #pragma unroll
                for (int mt = 0; mt < 4; ++mt)
                    mma_tf32(acc[mt][nt], af[mt][0], af[mt][1], af[mt][2], af[mt][3], b0, b1);
            }
        }
        __syncthreads();
    }

    #pragma unroll
    for (int mt = 0; mt < 4; ++mt) {
        int r = row0 + wm * 64 + mt * 16 + g;
        #pragma unroll
        for (int nt = 0; nt < 4; ++nt) {
            int c = col0 + wn * 32 + nt * 8 + t2;
            *reinterpret_cast<float2*>(&Cp[(size_t)r * 512 + c]) =
                make_float2(acc[mt][nt][0], acc[mt][nt][1]);
            *reinterpret_cast<float2*>(&Cp[(size_t)(r + 8) * 512 + c]) =
                make_float2(acc[mt][nt][2], acc[mt][nt][3]);
        }
    }
}

// =================== K3: fused stats + LN + output GEMM + gate ===================
// Block: 64 rows. t tile (64x128) and full weight (128x128) resident in smem,
// stats computed in-kernel, K=128 mainloop with no staging syncs.
// smem: A 128x72 | W 128x132 | red 2x256 | mu 64 | rs 64 | wd 128 | bd 128
#define B_A   0
#define B_W   36864
#define B_RS  104448
#define B_RQ  105472
#define B_MU  106496
#define B_RSI 106752
#define B_WD  107008
#define B_BD  107520
#define B_TOTAL 108032

__global__ void __launch_bounds__(256) k_back(const float* __restrict__ now,
                                              const float* __restrict__ nob,
                                              const float* __restrict__ powt,
                                              float* __restrict__ out) {
    extern __shared__ __align__(16) char smraw[];
    float*    Af  = reinterpret_cast<float*>(smraw + B_A);   // [d][row] stride 72
    uint32_t* Au  = reinterpret_cast<uint32_t*>(smraw + B_A);
    float*    Wf  = reinterpret_cast<float*>(smraw + B_W);   // [col][k] stride 132
    uint32_t* Wu  = reinterpret_cast<uint32_t*>(smraw + B_W);
    float*    reds = reinterpret_cast<float*>(smraw + B_RS);
    float*    redq = reinterpret_cast<float*>(smraw + B_RQ);
    float*    smu  = reinterpret_cast<float*>(smraw + B_MU);
    float*    srs  = reinterpret_cast<float*>(smraw + B_RSI);
    float*    swd  = reinterpret_cast<float*>(smraw + B_WD);
    float*    sbd  = reinterpret_cast<float*>(smraw + B_BD);

    const int tid = threadIdx.x;
    const int row0 = blockIdx.x * 64;
    const uint32_t sbase = (uint32_t)__cvta_generic_to_shared(smraw);
    const int w = tid >> 5;
    const int wm = w & 3;
    const int hf = w >> 2;
    const int lane = tid & 31;
    const int g = lane >> 2;
    const int t = lane & 3;
    const int t2 = t * 2;

    // ---- load t tile (d-major gmem -> [d][row] smem) + weights ----
    for (int s = tid; s < 2048; s += 256) {
        int d = s >> 4, r4 = (s & 15) * 4;
        cpa16(sbase + (uint32_t)(B_A) + (d * 72 + r4) * 4,
              g_t + (size_t)d * RR + row0 + r4);
    }
    for (int s = tid; s < 4096; s += 256) {
        int col = s >> 5, kg = s & 31;
        cpa16(sbase + (uint32_t)(B_W) + (col * 132 + kg * 4) * 4,
              powt + (size_t)col * 128 + kg * 4);
    }
    if (tid < 128) { swd[tid] = now[tid]; sbd[tid] = nob[tid]; }
    cpa_commit(); cpa_wait<0>(); __syncthreads();

    // ---- stats: 4 threads per row over d ----
    {
        int rr = tid & 63, q = tid >> 6;
        float s = 0.f, sq = 0.f;
        #pragma unroll 8
        for (int d = q * 32; d < q * 32 + 32; ++d) {
            float v = Af[d * 72 + rr];
            s += v; sq += v * v;
        }
        reds[q * 64 + rr] = s;
        redq[q * 64 + rr] = sq;
    }
    __syncthreads();
    if (tid < 64) {
        float S = reds[tid] + reds[64 + tid] + reds[128 + tid] + reds[192 + tid];
        float Q = redq[tid] + redq[64 + tid] + redq[128 + tid] + redq[192 + tid];
        float mu = S * (1.0f / 128.0f);
        smu[tid] = mu;
        srs[tid] = rsqrtf(Q * (1.0f / 128.0f) - mu * mu + 1e-5f);
    }
    __syncthreads();

    // ---- normalize + convert A in place; convert W in place ----
    for (int s = tid; s < 8192; s += 256) {
        int d = s >> 6, rr = s & 63;
        float v = Af[d * 72 + rr];
        Au[d * 72 + rr] = f2tf((v - smu[rr]) * srs[rr] * swd[d] + sbd[d]);
    }
    for (int s = tid; s < 16384; s += 256) {
        int col = s >> 7, k = s & 127;
        int idx = col * 132 + k;
        Wu[idx] = f2tf(Wf[idx]);
    }
    __syncthreads();

    // ---- mainloop: K=128 resident, no syncs ----
    float acc[8][4];
    #pragma unroll
    for (int i = 0; i < 8; ++i)
        #pragma unroll
        for (int j = 0; j < 4; ++j) acc[i][j] = 0.f;

    const int arow = wm * 16 + g;
    #pragma unroll 4
    for (int kk = 0; kk < 128; kk += 8) {
        uint32_t a0 = Au[(kk + t) * 72 + arow];
        uint32_t a1 = Au[(kk + t) * 72 + arow + 8];
        uint32_t a2 = Au[(kk + t + 4) * 72 + arow];
        uint32_t a3 = Au[(kk + t + 4) * 72 + arow + 8];
        #pragma unroll
        for (int nt = 0; nt < 8; ++nt) {
            int ncol = hf * 64 + nt * 8 + g;
            uint32_t b0 = Wu[ncol * 132 + kk + t];
            uint32_t b1 = Wu[ncol * 132 + kk + t + 4];
            mma_tf32(acc[nt], a0, a1, a2, a3, b0, b1);
        }
    }

    // ---- epilogue: gate + store ----
    #pragma unroll
    for (int nt = 0; nt < 8; ++nt) {
        int col = hf * 64 + nt * 8 + t2;
        int row = row0 + wm * 16 + g;
        float2 gt0 = *reinterpret_cast<const float2*>(&g_gate[(size_t)row * 128 + col]);
        float2 gt1 = *reinterpret_cast<const float2*>(&g_gate[(size_t)(row + 8) * 128 + col]);
        *reinterpret_cast<float2*>(&out[(size_t)row * 128 + col]) =
            make_float2(acc[nt][0] * gt0.x, acc[nt][1] * gt0.y);
        *reinterpret_cast<float2*>(&out[(size_t)(row + 8) * 128 + col]) =
            make_float2(acc[nt][2] * gt1.x, acc[nt][3] * gt1.y);
    }
}

// ---------------- launch ----------------
extern "C" void kernel_launch(void* const* d_in, const int* in_sizes, int n_in,
                              void* d_out, int out_size) {
    (void)in_sizes; (void)n_in; (void)out_size;
    const float* x    = (const float*)d_in[0];
    const float* niw  = (const float*)d_in[1];
    const float* nib  = (const float*)d_in[2];
    const float* piw  = (const float*)d_in[3];
    const float* giw  = (const float*)d_in[4];
    const float* noww = (const float*)d_in[5];
    const float* nob  = (const float*)d_in[6];
    const float* powt = (const float*)d_in[7];
    const float* gow  = (const float*)d_in[8];
    float* out = (float*)d_out;

    cudaFuncSetAttribute(k_front, cudaFuncAttributeMaxDynamicSharedMemorySize, F_TOTAL);
    cudaFuncSetAttribute(k_back,  cudaFuncAttributeMaxDynamicSharedMemorySize, B_TOTAL);

    k_front<<<RR / 128, 256, F_TOTAL>>>(x, niw, nib, piw, giw, gow);
    k_einsum<<<dim3(4, 4, 128), 256>>>();
    k_back<<<RR / 64, 256, B_TOTAL>>>(noww, nob, powt, out);
}